// round 2
// baseline (speedup 1.0000x reference)
#include <cuda_runtime.h>

#define BSZ 8
#define T 4096
#define DM 1024
#define CHL 32               // chunk length (rows per block)
#define NCH (T / CHL)        // 128 chunks per batch
#define TGRP 16              // rows batched per LN reduction round
#define LN_EPS 1e-5f

// Scratch (device globals; no cudaMalloc allowed)
__device__ float g_agg [BSZ * NCH * DM];   // chunk-local end state
__device__ float g_incl[BSZ * NCH * DM];   // inclusive end state
__device__ volatile int g_flag[BSZ * NCH]; // 0=empty, 1=aggregate, 2=inclusive
__device__ unsigned int g_ticket;

// ---------------------------------------------------------------------------
// Init: reset flags + ticket (runs before the main kernel on every replay)
// ---------------------------------------------------------------------------
__global__ void ssm_init()
{
    int i = blockIdx.x * blockDim.x + threadIdx.x;
    if (i < BSZ * NCH) g_flag[i] = 0;
    if (i == 0) g_ticket = 0u;
}

// ---------------------------------------------------------------------------
// Fused single-pass SSM + LayerNorm with decoupled lookback.
// Block = 1024 threads = one thread per channel. Each block owns one
// (batch, chunk) tile of 32 timesteps; y lives in registers end-to-end.
// ---------------------------------------------------------------------------
__global__ void __launch_bounds__(DM, 1) ssm_fused(
    const float* __restrict__ x,
    const float* __restrict__ A,
    const float* __restrict__ B,
    const float* __restrict__ C,
    const float* __restrict__ D,
    const float* __restrict__ gamma,
    const float* __restrict__ beta,
    float* __restrict__ out)
{
    __shared__ unsigned s_vid;
    __shared__ int s_flag;
    __shared__ float s_sum[TGRP][33];
    __shared__ float s_sq [TGRP][33];
    __shared__ float s_mu [TGRP];
    __shared__ float s_rs [TGRP];

    const int d    = threadIdx.x;
    const int lane = d & 31;
    const int w    = d >> 5;

    // Ticket: virtual block id in scheduling order -> lookback chains always
    // point at blocks that are resident or retired (no deadlock).
    if (d == 0) s_vid = atomicAdd(&g_ticket, 1u);
    __syncthreads();
    const unsigned vid = s_vid;
    const int b = vid & (BSZ - 1);
    const int c = (int)(vid >> 3);
    const int own = b * NCH + c;

    const float a  = A[d];
    const float bb = B[d];
    const float cc = C[d];
    const float dd = D[d];
    const float g  = gamma[d];
    const float be = beta[d];

    const size_t base = ((size_t)b * T + (size_t)c * CHL) * DM + d;

    // ---- Phase 1: local scan from zero state; y_local kept in registers ----
    float y[CHL];
    float h = 0.0f;
#pragma unroll
    for (int t = 0; t < CHL; ++t) {
        const float xv = x[base + (size_t)t * DM];
        h = fmaf(a, h, bb * xv);
        y[t] = fmaf(cc, h, dd * xv);
    }

    // aL = a^CHL via 5 squarings (CHL = 32)
    float aL = a;
    aL *= aL; aL *= aL; aL *= aL; aL *= aL; aL *= aL;

    // ---- Publish aggregate ASAP so successors can make progress ----
    if (c > 0) {
        g_agg[(size_t)own * DM + d] = h;
        __syncthreads();
        if (d == 0) { __threadfence(); g_flag[own] = 1; }
    }

    // ---- Lookback: h_start = sum over predecessors of aL^k * agg ----
    float carry = 0.0f;
    float factor = 1.0f;
    if (c > 0) {
        int j = c - 1;
        bool done = false;
        while (!done) {
            if (d == 0) {
                int f;
                do { f = g_flag[b * NCH + j]; } while (f == 0);
                s_flag = f;
            }
            __syncthreads();
            const int f = s_flag;
            __syncthreads();              // protect s_flag before next rewrite
            __threadfence();              // acquire: order flag read before data read
            if (f == 2) {
                carry = fmaf(factor, g_incl[(size_t)(b * NCH + j) * DM + d], carry);
                done = true;
            } else {
                carry = fmaf(factor, g_agg[(size_t)(b * NCH + j) * DM + d], carry);
                factor *= aL;
                --j;
            }
        }
    }
    const float h_start = carry;

    // ---- Publish inclusive state ----
    g_incl[(size_t)own * DM + d] = fmaf(aL, h_start, h);
    __syncthreads();
    if (d == 0) { __threadfence(); g_flag[own] = 2; }

    // ---- Correction: y_t += C * a^(t+1) * h_start ----
    const float k = cc * h_start;
    float pw = a;
#pragma unroll
    for (int t = 0; t < CHL; ++t) {
        y[t] = fmaf(pw, k, y[t]);
        pw *= a;
    }

    // ---- Fused LayerNorm over DM per row, TGRP rows per reduction round ----
    for (int grp = 0; grp < CHL / TGRP; ++grp) {
#pragma unroll
        for (int tt = 0; tt < TGRP; ++tt) {
            const float yv = y[grp * TGRP + tt];
            float s = yv;
            float q = yv * yv;
#pragma unroll
            for (int o = 16; o > 0; o >>= 1) {
                s += __shfl_xor_sync(0xFFFFFFFFu, s, o);
                q += __shfl_xor_sync(0xFFFFFFFFu, q, o);
            }
            if (lane == 0) {
                s_sum[tt][w] = s;
                s_sq [tt][w] = q;
            }
        }

        __syncthreads();

        if (w < TGRP) {
            float s = s_sum[w][lane];
            float q = s_sq [w][lane];
#pragma unroll
            for (int o = 16; o > 0; o >>= 1) {
                s += __shfl_xor_sync(0xFFFFFFFFu, s, o);
                q += __shfl_xor_sync(0xFFFFFFFFu, q, o);
            }
            if (lane == 0) {
                const float mu  = s * (1.0f / DM);
                const float var = q * (1.0f / DM) - mu * mu;
                s_mu[w] = mu;
                s_rs[w] = rsqrtf(var + LN_EPS);
            }
        }

        __syncthreads();

#pragma unroll
        for (int tt = 0; tt < TGRP; ++tt) {
            const int t = grp * TGRP + tt;
            out[base + (size_t)t * DM] =
                fmaf((y[t] - s_mu[tt]) * s_rs[tt], g, be);
        }
        __syncthreads();   // s_sum/s_mu reused next group
    }
}

// ---------------------------------------------------------------------------
// Launch. Inputs (metadata order): x, A, B, C, D, gamma, beta. Output: fp32.
// ---------------------------------------------------------------------------
extern "C" void kernel_launch(void* const* d_in, const int* in_sizes, int n_in,
                              void* d_out, int out_size)
{
    const float* x     = (const float*)d_in[0];
    const float* A     = (const float*)d_in[1];
    const float* B     = (const float*)d_in[2];
    const float* C     = (const float*)d_in[3];
    const float* D     = (const float*)d_in[4];
    const float* gamma = (const float*)d_in[5];
    const float* beta  = (const float*)d_in[6];
    float* out = (float*)d_out;

    ssm_init<<<1, DM>>>();
    ssm_fused<<<BSZ * NCH, DM>>>(x, A, B, C, D, gamma, beta, out);
}

// round 3
// speedup vs baseline: 1.5342x; 1.5342x over previous
#include <cuda_runtime.h>

#define BSZ 8
#define T 4096
#define DM 1024
#define VEC 4
#define NTH (DM / VEC)        // 256 threads = one float4 lane per thread
#define CHL 64                // chunk length (timesteps per chunk)
#define NCH (T / CHL)         // 64 chunks per batch
#define TGRP 16               // rows batched per LN reduction round
#define NW (NTH / 32)         // 8 warps
#define LN_EPS 1e-5f

// Scratch (device globals; no cudaMalloc allowed)
__device__ float4 g_hlocal[BSZ * NCH * NTH];
__device__ float4 g_hstart[BSZ * NCH * NTH];

// ---------------------------------------------------------------------------
// Pass 1: per (b, c) chunk, local scan from zero state. float4-vectorized.
// ---------------------------------------------------------------------------
__global__ void __launch_bounds__(NTH) ssm_pass1(
    const float4* __restrict__ x,
    const float4* __restrict__ A,
    const float4* __restrict__ B)
{
    const int d = threadIdx.x;           // float4 lane (0..255)
    const int c = blockIdx.x;
    const int b = blockIdx.y;

    const float4 a  = A[d];
    const float4 bb = B[d];

    const float4* __restrict__ xp =
        x + ((size_t)b * T + (size_t)c * CHL) * NTH + d;

    float4 h = make_float4(0.f, 0.f, 0.f, 0.f);
#pragma unroll 8
    for (int t = 0; t < CHL; ++t) {
        const float4 xv = xp[(size_t)t * NTH];
        h.x = fmaf(a.x, h.x, bb.x * xv.x);
        h.y = fmaf(a.y, h.y, bb.y * xv.y);
        h.z = fmaf(a.z, h.z, bb.z * xv.z);
        h.w = fmaf(a.w, h.w, bb.w * xv.w);
    }
    g_hlocal[((b * NCH) + c) * NTH + d] = h;
}

// ---------------------------------------------------------------------------
// Combine: serial prefix over chunk aggregates (per b, d lane).
// ---------------------------------------------------------------------------
__global__ void ssm_combine(const float4* __restrict__ A)
{
    const int idx = blockIdx.x * blockDim.x + threadIdx.x;  // over BSZ*NTH
    const int d = idx & (NTH - 1);
    const int b = idx >> 8;                                 // / NTH

    const float4 a = A[d];
    float4 aL = a;                                          // a^64: 6 squarings
#pragma unroll
    for (int i = 0; i < 6; ++i) {
        aL.x *= aL.x; aL.y *= aL.y; aL.z *= aL.z; aL.w *= aL.w;
    }

    float4 carry = make_float4(0.f, 0.f, 0.f, 0.f);
#pragma unroll 4
    for (int c = 0; c < NCH; ++c) {
        const int o = (b * NCH + c) * NTH + d;
        g_hstart[o] = carry;
        const float4 hl = g_hlocal[o];
        carry.x = fmaf(aL.x, carry.x, hl.x);
        carry.y = fmaf(aL.y, carry.y, hl.y);
        carry.z = fmaf(aL.z, carry.z, hl.z);
        carry.w = fmaf(aL.w, carry.w, hl.w);
    }
}

// ---------------------------------------------------------------------------
// Pass 2: recurrence from correct h_start + fused LayerNorm.
// 256 threads/block, 4 channels/thread, TGRP=16 rows per reduction round,
// y rows truly register-resident (<=128 regs, 2 CTAs/SM).
// ---------------------------------------------------------------------------
__global__ void __launch_bounds__(NTH, 2) ssm_pass2(
    const float4* __restrict__ x,
    const float4* __restrict__ A,
    const float4* __restrict__ B,
    const float4* __restrict__ C,
    const float4* __restrict__ D,
    const float4* __restrict__ gamma,
    const float4* __restrict__ beta,
    float4* __restrict__ out)
{
    __shared__ float s_sum[TGRP][NW + 1];
    __shared__ float s_sq [TGRP][NW + 1];
    __shared__ float s_mu [TGRP];
    __shared__ float s_rs [TGRP];

    const int d    = threadIdx.x;
    const int lane = d & 31;
    const int w    = d >> 5;            // 0..7
    const int c    = blockIdx.x;
    const int b    = blockIdx.y;

    const float4 a  = A[d];
    const float4 bb = B[d];
    const float4 cc = C[d];
    const float4 dd = D[d];
    const float4 g  = gamma[d];
    const float4 be = beta[d];

    float4 h = g_hstart[(b * NCH + c) * NTH + d];

    const size_t base = ((size_t)b * T + (size_t)c * CHL) * NTH + d;

    for (int grp = 0; grp < CHL / TGRP; ++grp) {
        float4 y[TGRP];

#pragma unroll
        for (int tt = 0; tt < TGRP; ++tt) {
            const float4 xv = x[base + (size_t)(grp * TGRP + tt) * NTH];
            h.x = fmaf(a.x, h.x, bb.x * xv.x);
            h.y = fmaf(a.y, h.y, bb.y * xv.y);
            h.z = fmaf(a.z, h.z, bb.z * xv.z);
            h.w = fmaf(a.w, h.w, bb.w * xv.w);
            float4 yv;
            yv.x = fmaf(cc.x, h.x, dd.x * xv.x);
            yv.y = fmaf(cc.y, h.y, dd.y * xv.y);
            yv.z = fmaf(cc.z, h.z, dd.z * xv.z);
            yv.w = fmaf(cc.w, h.w, dd.w * xv.w);
            y[tt] = yv;

            // thread-local 4->1, then warp reduce (32 lanes)
            float s = (yv.x + yv.y) + (yv.z + yv.w);
            float q = fmaf(yv.x, yv.x, yv.y * yv.y) +
                      fmaf(yv.z, yv.z, yv.w * yv.w);
#pragma unroll
            for (int o = 16; o > 0; o >>= 1) {
                s += __shfl_xor_sync(0xFFFFFFFFu, s, o);
                q += __shfl_xor_sync(0xFFFFFFFFu, q, o);
            }
            if (lane == 0) {
                s_sum[tt][w] = s;
                s_sq [tt][w] = q;
            }
        }

        __syncthreads();

        // each warp finishes 2 rows: r = w and w + 8
#pragma unroll
        for (int rr = 0; rr < 2; ++rr) {
            const int r = w + rr * NW;
            float s = (lane < NW) ? s_sum[r][lane] : 0.f;
            float q = (lane < NW) ? s_sq [r][lane] : 0.f;
#pragma unroll
            for (int o = NW / 2; o > 0; o >>= 1) {
                s += __shfl_xor_sync(0xFFFFFFFFu, s, o);
                q += __shfl_xor_sync(0xFFFFFFFFu, q, o);
            }
            if (lane == 0) {
                const float mu  = s * (1.0f / DM);
                const float var = q * (1.0f / DM) - mu * mu;
                s_mu[r] = mu;
                s_rs[r] = rsqrtf(var + LN_EPS);
            }
        }

        __syncthreads();

#pragma unroll
        for (int tt = 0; tt < TGRP; ++tt) {
            const float4 yv = y[tt];
            const float mu = s_mu[tt];
            const float rs = s_rs[tt];
            float4 o;
            o.x = fmaf((yv.x - mu) * rs, g.x, be.x);
            o.y = fmaf((yv.y - mu) * rs, g.y, be.y);
            o.z = fmaf((yv.z - mu) * rs, g.z, be.z);
            o.w = fmaf((yv.w - mu) * rs, g.w, be.w);
            out[base + (size_t)(grp * TGRP + tt) * NTH] = o;
        }
        // no trailing barrier: next group's first __syncthreads orders the
        // s_mu/s_rs rewrite against these reads (program order per thread).
    }
}

// ---------------------------------------------------------------------------
// Launch. Inputs (metadata order): x, A, B, C, D, gamma, beta. Output: fp32.
// ---------------------------------------------------------------------------
extern "C" void kernel_launch(void* const* d_in, const int* in_sizes, int n_in,
                              void* d_out, int out_size)
{
    const float4* x     = (const float4*)d_in[0];
    const float4* A     = (const float4*)d_in[1];
    const float4* B     = (const float4*)d_in[2];
    const float4* C     = (const float4*)d_in[3];
    const float4* D     = (const float4*)d_in[4];
    const float4* gamma = (const float4*)d_in[5];
    const float4* beta  = (const float4*)d_in[6];
    float4* out = (float4*)d_out;

    dim3 grid(NCH, BSZ);

    ssm_pass1<<<grid, NTH>>>(x, A, B);
    ssm_combine<<<(BSZ * NTH) / 256, 256>>>(A);
    ssm_pass2<<<grid, NTH>>>(x, A, B, C, D, gamma, beta, out);
}